// round 14
// baseline (speedup 1.0000x reference)
#include <cuda_runtime.h>
#include <cuda_fp16.h>
#include <mma.h>
using namespace nvcuda;

#define NN 50000
#define NE 800000
#define NF 256
#define NH 64
#define NC 40
#define EPSR 0.3f
#define CAP 128                       // fixed per-node slot capacity
#define MT 128                        // gemm M-tile (nodes per block)
#define KC 32                         // gemm K-chunk
#define ALD 36                        // A smem leading dim
#define BLD 36                        // B smem leading dim
#define HLD 68                        // epilogue smem leading dim
#define AGG_NPB 32                    // nodes per agg block (half-warp each)

// ---- device scratch ----
__device__ __align__(128) int     g_deg[NN];
__device__ __align__(128) int     g_fill[NN];      // doubles as incoming-count after bucket
__device__ __align__(128) float   g_ci[NN];        // nd[n]/max(cnt,1)
__device__ __align__(128) float   g_s2[NN];
__device__ __align__(128) float   g_snA[2 * NN];   // {s1_layer0, nd}
__device__ __align__(128) float   g_snB[2 * NN];   // {s1_layer1, nd}
__device__ __align__(128) int     g_srcA[NN * CAP];
__device__ __align__(128) float   g_h[NN * NH];    // layer-0 h == raw (fp32)
__device__ __align__(128) float   g_h2[NN * NH];   // layer-1 input (fp32)
__device__ __align__(128) __half2 g_hh[NN * NH / 2];
__device__ __align__(128) __half2 g_hh2[NN * NH / 2];

__device__ __forceinline__ float ftanh(float x) {
    x = fminf(fmaxf(x, -20.0f), 20.0f);
    float t = __expf(2.0f * x);
    return __fdividef(t - 1.0f, t + 1.0f);
}

__device__ __forceinline__ float pack_h2(float a, float b) {
    __half2 h = __floats2half2_rn(a, b);
    return *(float*)&h;
}

// fused bucketing + degree histogram: 8 edges per thread (16 indep atomic chains)
__global__ void k_bucket(const int* __restrict__ ei) {
    int t = blockIdx.x * blockDim.x + threadIdx.x;
    if (t >= NE / 8) return;
    int4 ra = ((const int4*)ei)[2 * t];
    int4 rb = ((const int4*)ei)[2 * t + 1];
    int4 ca = ((const int4*)(ei + NE))[2 * t];
    int4 cb = ((const int4*)(ei + NE))[2 * t + 1];
    atomicAdd(&g_deg[ra.x], 1);
    atomicAdd(&g_deg[ra.y], 1);
    atomicAdd(&g_deg[ra.z], 1);
    atomicAdd(&g_deg[ra.w], 1);
    atomicAdd(&g_deg[rb.x], 1);
    atomicAdd(&g_deg[rb.y], 1);
    atomicAdd(&g_deg[rb.z], 1);
    atomicAdd(&g_deg[rb.w], 1);
    int s0 = atomicAdd(&g_fill[ca.x], 1);
    int s1 = atomicAdd(&g_fill[ca.y], 1);
    int s2 = atomicAdd(&g_fill[ca.z], 1);
    int s3 = atomicAdd(&g_fill[ca.w], 1);
    int s4 = atomicAdd(&g_fill[cb.x], 1);
    int s5 = atomicAdd(&g_fill[cb.y], 1);
    int s6 = atomicAdd(&g_fill[cb.z], 1);
    int s7 = atomicAdd(&g_fill[cb.w], 1);
    g_srcA[(ca.x << 7) + s0] = ra.x;
    g_srcA[(ca.y << 7) + s1] = ra.y;
    g_srcA[(ca.z << 7) + s2] = ra.z;
    g_srcA[(ca.w << 7) + s3] = ra.w;
    g_srcA[(cb.x << 7) + s4] = rb.x;
    g_srcA[(cb.y << 7) + s5] = rb.y;
    g_srcA[(cb.z << 7) + s6] = rb.z;
    g_srcA[(cb.w << 7) + s7] = rb.w;
}

// per-node prep (cnt comes from fill after bucket)
__global__ void k_nodeprep() {
    int i = blockIdx.x * blockDim.x + threadIdx.x;
    if (i >= NN) return;
    int d = g_deg[i]; if (d < 1) d = 1;
    float nd = rsqrtf((float)d);
    int c = g_fill[i]; if (c < 1) c = 1;
    g_ci[i] = nd / (float)c;
    g_snA[2 * i + 1] = nd;
    g_snB[2 * i + 1] = nd;
}

// tf32 wmma GEMM, 128x64 block tile, K-chunk 32, smem-staged operands.
__global__ __launch_bounds__(256) void k_gemm1(const float* __restrict__ x,
                                               const float* __restrict__ W1,
                                               const float* __restrict__ b1,
                                               const float* __restrict__ gw) {
    __shared__ float pool[MT * HLD];          // 128*68 floats = 34.8 KB
    float* as = pool;                          // [128][ALD]
    float* bs = pool + MT * ALD;               // [64][BLD]

    int tid = threadIdx.x;
    int nb = blockIdx.x * MT;
    int warp = tid >> 5;                       // 0..7 : 16-row band

    wmma::fragment<wmma::accumulator, 16, 16, 8, float> acc[4];
#pragma unroll
    for (int c = 0; c < 4; c++) wmma::fill_fragment(acc[c], 0.0f);

    int arow = tid >> 1;                       // 0..127
    int kh   = tid & 1;                        // 0..1 : 16-float half
    int xrow = nb + arow; if (xrow >= NN) xrow = NN - 1;
    const float4* xr = (const float4*)(x + (size_t)xrow * NF);
    int brow = tid >> 2;                       // 0..63
    int bq   = tid & 3;                        // 0..3 : 8-float quarter
    const float4* wr4 = (const float4*)(W1 + (size_t)brow * NF);

    for (int k0 = 0; k0 < NF; k0 += KC) {
        float* ad = as + arow * ALD + kh * 16;
#pragma unroll
        for (int i = 0; i < 4; i++)
            ((float4*)ad)[i] = xr[(k0 >> 2) + kh * 4 + i];
        float* bd = bs + brow * BLD + bq * 8;
#pragma unroll
        for (int i = 0; i < 2; i++)
            ((float4*)bd)[i] = wr4[(k0 >> 2) + bq * 2 + i];
        __syncthreads();
#pragma unroll
        for (int kk = 0; kk < KC; kk += 8) {
            wmma::fragment<wmma::matrix_a, 16, 16, 8, wmma::precision::tf32,
                           wmma::row_major> a;
            wmma::load_matrix_sync(a, as + warp * 16 * ALD + kk, ALD);
#pragma unroll
            for (int q = 0; q < a.num_elements; q++)
                a.x[q] = wmma::__float_to_tf32(a.x[q]);
#pragma unroll
            for (int c = 0; c < 4; c++) {
                wmma::fragment<wmma::matrix_b, 16, 16, 8, wmma::precision::tf32,
                               wmma::col_major> bf;
                wmma::load_matrix_sync(bf, bs + (c * 16) * BLD + kk, BLD);
#pragma unroll
                for (int q = 0; q < bf.num_elements; q++)
                    bf.x[q] = wmma::__float_to_tf32(bf.x[q]);
                wmma::mma_sync(acc[c], a, bf, acc[c]);
            }
        }
        __syncthreads();
    }

#pragma unroll
    for (int c = 0; c < 4; c++)
        wmma::store_matrix_sync(pool + warp * 16 * HLD + c * 16, acc[c], HLD,
                                wmma::mem_row_major);
    __syncthreads();

    int row = tid >> 1;
    int jh  = tid & 1;
    int j0  = jh * 32;
    int n   = nb + row;
    float s1p = 0.0f, s2p = 0.0f;
    float hv[32];
#pragma unroll
    for (int i = 0; i < 32; i++) {
        float v = pool[row * HLD + j0 + i] + b1[j0 + i];
        v = fmaxf(v, 0.0f);
        hv[i] = v;
        s1p += v * gw[j0 + i];
        s2p += v * gw[NH + j0 + i];
    }
    if (n < NN) {
#pragma unroll
        for (int i = 0; i < 32; i += 4)
            *(float4*)(g_h + n * NH + j0 + i) =
                make_float4(hv[i], hv[i + 1], hv[i + 2], hv[i + 3]);
#pragma unroll
        for (int i = 0; i < 32; i += 8) {
            float4 pk;
            pk.x = pack_h2(hv[i    ], hv[i + 1]);
            pk.y = pack_h2(hv[i + 2], hv[i + 3]);
            pk.z = pack_h2(hv[i + 4], hv[i + 5]);
            pk.w = pack_h2(hv[i + 6], hv[i + 7]);
            *(float4*)&g_hh[n * 32 + (j0 + i) / 2] = pk;
        }
    }
    s1p += __shfl_xor_sync(0xffffffff, s1p, 1);
    s2p += __shfl_xor_sync(0xffffffff, s2p, 1);
    if (jh == 0 && n < NN) { g_snA[2 * n] = s1p; g_s2[n] = s2p; }
}

// fp16 half-warp gather body
#define AGG_GATHER_LOOP(HH)                                                      \
    int cnt = e - base; if (cnt > 16) cnt = 16;                                  \
    int ii = 0;                                                                  \
    for (; ii + 4 <= cnt; ii += 4) {                                             \
        int   r0 = s_src[hw][ii    ], r1 = s_src[hw][ii + 1];                    \
        int   r2 = s_src[hw][ii + 2], r3 = s_src[hw][ii + 3];                    \
        float n0 = s_nrm[hw][ii    ], n1 = s_nrm[hw][ii + 1];                    \
        float n2 = s_nrm[hw][ii + 2], n3 = s_nrm[hw][ii + 3];                    \
        float2 q0 = *(const float2*)(HH + r0 * 32 + lane2);                      \
        float2 q1 = *(const float2*)(HH + r1 * 32 + lane2);                      \
        float2 q2 = *(const float2*)(HH + r2 * 32 + lane2);                      \
        float2 q3 = *(const float2*)(HH + r3 * 32 + lane2);                      \
        float2 a0 = __half22float2(*(__half2*)&q0.x), b0 = __half22float2(*(__half2*)&q0.y); \
        float2 a1 = __half22float2(*(__half2*)&q1.x), b1v = __half22float2(*(__half2*)&q1.y); \
        float2 a2 = __half22float2(*(__half2*)&q2.x), b2v = __half22float2(*(__half2*)&q2.y); \
        float2 a3 = __half22float2(*(__half2*)&q3.x), b3v = __half22float2(*(__half2*)&q3.y); \
        acc.x += n0 * a0.x + n1 * a1.x + n2 * a2.x + n3 * a3.x;                  \
        acc.y += n0 * a0.y + n1 * a1.y + n2 * a2.y + n3 * a3.y;                  \
        acc.z += n0 * b0.x + n1 * b1v.x + n2 * b2v.x + n3 * b3v.x;               \
        acc.w += n0 * b0.y + n1 * b1v.y + n2 * b2v.y + n3 * b3v.y;               \
        ns    += n0 + n1 + n2 + n3;                                              \
    }                                                                            \
    for (; ii < cnt; ii++) {                                                     \
        int   rr = s_src[hw][ii];                                                \
        float nn = s_nrm[hw][ii];                                                \
        float2 qq = *(const float2*)(HH + rr * 32 + lane2);                      \
        float2 aa = __half22float2(*(__half2*)&qq.x);                            \
        float2 bb = __half22float2(*(__half2*)&qq.y);                            \
        acc.x += nn * aa.x; acc.y += nn * aa.y;                                  \
        acc.z += nn * bb.x; acc.w += nn * bb.y;                                  \
        ns    += nn;                                                             \
    }

// layer-0 aggregation (half-warp per node) + layer-1 gate scalars
__global__ __launch_bounds__(16 * AGG_NPB) void k_agg0(const float* __restrict__ gw_next,
                                                       const float* __restrict__ gb) {
    __shared__ int   s_src[AGG_NPB][16];
    __shared__ float s_nrm[AGG_NPB][16];
    int tid  = threadIdx.x;
    int hw   = tid >> 4;
    int lane = tid & 15;
    unsigned mask = (tid & 16) ? 0xFFFF0000u : 0x0000FFFFu;
    int n = blockIdx.x * AGG_NPB + hw;
    if (n >= NN) return;

    int b = n << 7;
    int e = b + g_fill[n];
    float s2n = g_s2[n] + gb[0];
    float4 acc = make_float4(0.0f, 0.0f, 0.0f, 0.0f);
    float  ns  = 0.0f;
    int j4 = lane * 4;
    int lane2 = lane * 2;

    for (int base = b; base < e; base += 16) {
        int p = base + lane;
        int r = 0; float nm = 0.0f;
        if (p < e) {
            r = g_srcA[p];
            float2 sn = *(const float2*)(g_snA + 2 * r);
            nm = ftanh(sn.x + s2n) * sn.y;
        }
        s_src[hw][lane] = r;
        s_nrm[hw][lane] = nm;
        __syncwarp(mask);
        AGG_GATHER_LOOP(g_hh)
        __syncwarp(mask);
    }

    float4 hself = *(const float4*)(g_h + n * NH + j4);
    float ci = g_ci[n];
    float4 ho;
    ho.x = EPSR * hself.x + (acc.x + hself.x * ns) * ci;
    ho.y = EPSR * hself.y + (acc.y + hself.y * ns) * ci;
    ho.z = EPSR * hself.z + (acc.z + hself.z * ns) * ci;
    ho.w = EPSR * hself.w + (acc.w + hself.w * ns) * ci;
    *(float4*)(g_h2 + n * NH + j4) = ho;
    {
        float2 pk;
        pk.x = pack_h2(ho.x, ho.y);
        pk.y = pack_h2(ho.z, ho.w);
        *(float2*)&g_hh2[n * 32 + lane2] = pk;
    }

    float4 ga = *(const float4*)(gw_next + j4);
    float4 gbv = *(const float4*)(gw_next + NH + j4);
    float p1 = ho.x * ga.x + ho.y * ga.y + ho.z * ga.z + ho.w * ga.w;
    float p2 = ho.x * gbv.x + ho.y * gbv.y + ho.z * gbv.z + ho.w * gbv.w;
#pragma unroll
    for (int off = 8; off > 0; off >>= 1) {
        p1 += __shfl_xor_sync(mask, p1, off);
        p2 += __shfl_xor_sync(mask, p2, off);
    }
    if (lane == 0) { g_snB[2 * n] = p1; g_s2[n] = p2; }
}

// layer-1 aggregation fused with classifier + log_softmax
__global__ __launch_bounds__(16 * AGG_NPB) void k_agg1_out(const float* __restrict__ gb,
                                                           const float* __restrict__ W2,
                                                           const float* __restrict__ b2,
                                                           float* __restrict__ out) {
    __shared__ int   s_src[AGG_NPB][16];
    __shared__ float s_nrm[AGG_NPB][16];
    __shared__ float s_h[AGG_NPB][NH];
    __shared__ float sW2t[NH * NC];
    __shared__ float sb2[NC];

    int tid  = threadIdx.x;
    int hw   = tid >> 4;
    int lane = tid & 15;
    unsigned mask = (tid & 16) ? 0xFFFF0000u : 0x0000FFFFu;
    int n = blockIdx.x * AGG_NPB + hw;

    for (int idx = tid; idx < NC * NH; idx += 16 * AGG_NPB) {
        int c = idx >> 6, j = idx & 63;
        sW2t[j * NC + c] = W2[idx];
    }
    if (tid < NC) sb2[tid] = b2[tid];
    __syncthreads();
    if (n >= NN) return;

    int b = n << 7;
    int e = b + g_fill[n];
    float s2n = g_s2[n] + gb[1];
    float4 acc = make_float4(0.0f, 0.0f, 0.0f, 0.0f);
    float  ns  = 0.0f;
    int j4 = lane * 4;
    int lane2 = lane * 2;

    for (int base = b; base < e; base += 16) {
        int p = base + lane;
        int r = 0; float nm = 0.0f;
        if (p < e) {
            r = g_srcA[p];
            float2 sn = *(const float2*)(g_snB + 2 * r);
            nm = ftanh(sn.x + s2n) * sn.y;
        }
        s_src[hw][lane] = r;
        s_nrm[hw][lane] = nm;
        __syncwarp(mask);
        AGG_GATHER_LOOP(g_hh2)
        __syncwarp(mask);
    }

    float4 hself = *(const float4*)(g_h2 + n * NH + j4);
    float4 rawv  = *(const float4*)(g_h  + n * NH + j4);
    float ci = g_ci[n];
    float4 ho;
    ho.x = EPSR * rawv.x + (acc.x + hself.x * ns) * ci;
    ho.y = EPSR * rawv.y + (acc.y + hself.y * ns) * ci;
    ho.z = EPSR * rawv.z + (acc.z + hself.z * ns) * ci;
    ho.w = EPSR * rawv.w + (acc.w + hself.w * ns) * ci;
    *(float4*)&s_h[hw][j4] = ho;
    __syncwarp(mask);

    int c0 = lane, c1 = lane + 16, c2 = lane + 32;
    bool has2 = (c2 < NC);
    float l0 = sb2[c0];
    float l1 = sb2[c1];
    float l2 = has2 ? sb2[c2] : -3.0e38f;
#pragma unroll 8
    for (int j = 0; j < NH; j++) {
        float hv = s_h[hw][j];
        l0 += hv * sW2t[j * NC + c0];
        l1 += hv * sW2t[j * NC + c1];
        if (has2) l2 += hv * sW2t[j * NC + c2];
    }
    float m = fmaxf(fmaxf(l0, l1), l2);
#pragma unroll
    for (int off = 8; off > 0; off >>= 1)
        m = fmaxf(m, __shfl_xor_sync(mask, m, off));
    float s = expf(l0 - m) + expf(l1 - m) + (has2 ? expf(l2 - m) : 0.0f);
#pragma unroll
    for (int off = 8; off > 0; off >>= 1)
        s += __shfl_xor_sync(mask, s, off);
    float lse = m + logf(s);
    float* o = out + (size_t)n * NC;
    o[c0] = l0 - lse;
    o[c1] = l1 - lse;
    if (has2) o[c2] = l2 - lse;
}

extern "C" void kernel_launch(void* const* d_in, const int* in_sizes, int n_in,
                              void* d_out, int out_size) {
    const float* x  = (const float*)d_in[0];
    const int*   ei = (const int*)d_in[1];    // int32 (jax x64 disabled)
    const float* W1 = (const float*)d_in[2];
    const float* b1 = (const float*)d_in[3];
    const float* W2 = (const float*)d_in[4];
    const float* b2 = (const float*)d_in[5];
    const float* gw = (const float*)d_in[6];
    const float* gb = (const float*)d_in[7];
    float* out = (float*)d_out;

    static cudaStream_t sB = nullptr;
    static cudaEvent_t evRoot = nullptr, evJoinB = nullptr;
    static void* pDeg = nullptr; static void* pFill = nullptr;
    if (!sB) {
        cudaStreamCreateWithFlags(&sB, cudaStreamNonBlocking);
        cudaEventCreateWithFlags(&evRoot, cudaEventDisableTiming);
        cudaEventCreateWithFlags(&evJoinB, cudaEventDisableTiming);
        cudaGetSymbolAddress(&pDeg, g_deg);
        cudaGetSymbolAddress(&pFill, g_fill);
    }

    const int B = 256;

    cudaEventRecord(evRoot, 0);

    // branch B: gemm
    cudaStreamWaitEvent(sB, evRoot, 0);
    k_gemm1<<<(NN + MT - 1) / MT, 256, 0, sB>>>(x, W1, b1, gw);
    cudaEventRecord(evJoinB, sB);

    // default: memsets -> fused bucket(+deg) -> nodeprep
    cudaMemsetAsync(pDeg, 0, NN * sizeof(int), 0);
    cudaMemsetAsync(pFill, 0, NN * sizeof(int), 0);
    k_bucket<<<(NE / 8 + B - 1) / B, B>>>(ei);
    k_nodeprep<<<(NN + B - 1) / B, B>>>();

    cudaStreamWaitEvent(0, evJoinB, 0);

    k_agg0<<<(NN + AGG_NPB - 1) / AGG_NPB, 16 * AGG_NPB>>>(gw + 2 * NH, gb);
    k_agg1_out<<<(NN + AGG_NPB - 1) / AGG_NPB, 16 * AGG_NPB>>>(gb, W2, b2, out);
}

// round 15
// speedup vs baseline: 1.0687x; 1.0687x over previous
#include <cuda_runtime.h>
#include <cuda_fp16.h>
#include <mma.h>
using namespace nvcuda;

#define NN 50000
#define NE 800000
#define NF 256
#define NH 64
#define NC 40
#define EPSR 0.3f
#define CAP 128                       // fixed per-node slot capacity
#define MT 128                        // gemm M-tile (nodes per block)
#define KC 32                         // gemm K-chunk
#define ALD 36                        // A smem leading dim
#define BLD 36                        // B smem leading dim
#define HLD 68                        // epilogue smem leading dim
#define AGG_NPB 64                    // nodes per agg block (8-lane group each)
#define AGG_THREADS (8 * AGG_NPB)     // 512

// ---- device scratch ----
__device__ __align__(128) int     g_deg[NN];
__device__ __align__(128) int     g_fill[NN];      // doubles as incoming-count after bucket
__device__ __align__(128) float   g_ci[NN];        // nd[n]/max(cnt,1)
__device__ __align__(128) float   g_s2[NN];
__device__ __align__(128) float   g_snA[2 * NN];   // {s1_layer0, nd}
__device__ __align__(128) float   g_snB[2 * NN];   // {s1_layer1, nd}
__device__ __align__(128) int     g_srcA[NN * CAP];
__device__ __align__(128) float   g_h[NN * NH];    // layer-0 h == raw (fp32)
__device__ __align__(128) float   g_h2[NN * NH];   // layer-1 input (fp32)
__device__ __align__(128) __half2 g_hh[NN * NH / 2];
__device__ __align__(128) __half2 g_hh2[NN * NH / 2];

__device__ __forceinline__ float ftanh(float x) {
    x = fminf(fmaxf(x, -20.0f), 20.0f);
    float t = __expf(2.0f * x);
    return __fdividef(t - 1.0f, t + 1.0f);
}

__device__ __forceinline__ float pack_h2(float a, float b) {
    __half2 h = __floats2half2_rn(a, b);
    return *(float*)&h;
}

// fused bucketing + degree histogram: 8 edges per thread
__global__ void k_bucket(const int* __restrict__ ei) {
    int t = blockIdx.x * blockDim.x + threadIdx.x;
    if (t >= NE / 8) return;
    int4 ra = ((const int4*)ei)[2 * t];
    int4 rb = ((const int4*)ei)[2 * t + 1];
    int4 ca = ((const int4*)(ei + NE))[2 * t];
    int4 cb = ((const int4*)(ei + NE))[2 * t + 1];
    atomicAdd(&g_deg[ra.x], 1);
    atomicAdd(&g_deg[ra.y], 1);
    atomicAdd(&g_deg[ra.z], 1);
    atomicAdd(&g_deg[ra.w], 1);
    atomicAdd(&g_deg[rb.x], 1);
    atomicAdd(&g_deg[rb.y], 1);
    atomicAdd(&g_deg[rb.z], 1);
    atomicAdd(&g_deg[rb.w], 1);
    int s0 = atomicAdd(&g_fill[ca.x], 1);
    int s1 = atomicAdd(&g_fill[ca.y], 1);
    int s2 = atomicAdd(&g_fill[ca.z], 1);
    int s3 = atomicAdd(&g_fill[ca.w], 1);
    int s4 = atomicAdd(&g_fill[cb.x], 1);
    int s5 = atomicAdd(&g_fill[cb.y], 1);
    int s6 = atomicAdd(&g_fill[cb.z], 1);
    int s7 = atomicAdd(&g_fill[cb.w], 1);
    g_srcA[(ca.x << 7) + s0] = ra.x;
    g_srcA[(ca.y << 7) + s1] = ra.y;
    g_srcA[(ca.z << 7) + s2] = ra.z;
    g_srcA[(ca.w << 7) + s3] = ra.w;
    g_srcA[(cb.x << 7) + s4] = rb.x;
    g_srcA[(cb.y << 7) + s5] = rb.y;
    g_srcA[(cb.z << 7) + s6] = rb.z;
    g_srcA[(cb.w << 7) + s7] = rb.w;
}

// per-node prep (cnt comes from fill after bucket)
__global__ void k_nodeprep() {
    int i = blockIdx.x * blockDim.x + threadIdx.x;
    if (i >= NN) return;
    int d = g_deg[i]; if (d < 1) d = 1;
    float nd = rsqrtf((float)d);
    int c = g_fill[i]; if (c < 1) c = 1;
    g_ci[i] = nd / (float)c;
    g_snA[2 * i + 1] = nd;
    g_snB[2 * i + 1] = nd;
}

// tf32 wmma GEMM, 128x64 block tile, K-chunk 32, smem-staged operands.
__global__ __launch_bounds__(256) void k_gemm1(const float* __restrict__ x,
                                               const float* __restrict__ W1,
                                               const float* __restrict__ b1,
                                               const float* __restrict__ gw) {
    __shared__ float pool[MT * HLD];          // 128*68 floats = 34.8 KB
    float* as = pool;                          // [128][ALD]
    float* bs = pool + MT * ALD;               // [64][BLD]

    int tid = threadIdx.x;
    int nb = blockIdx.x * MT;
    int warp = tid >> 5;                       // 0..7 : 16-row band

    wmma::fragment<wmma::accumulator, 16, 16, 8, float> acc[4];
#pragma unroll
    for (int c = 0; c < 4; c++) wmma::fill_fragment(acc[c], 0.0f);

    int arow = tid >> 1;                       // 0..127
    int kh   = tid & 1;                        // 0..1 : 16-float half
    int xrow = nb + arow; if (xrow >= NN) xrow = NN - 1;
    const float4* xr = (const float4*)(x + (size_t)xrow * NF);
    int brow = tid >> 2;                       // 0..63
    int bq   = tid & 3;                        // 0..3 : 8-float quarter
    const float4* wr4 = (const float4*)(W1 + (size_t)brow * NF);

    for (int k0 = 0; k0 < NF; k0 += KC) {
        float* ad = as + arow * ALD + kh * 16;
#pragma unroll
        for (int i = 0; i < 4; i++)
            ((float4*)ad)[i] = xr[(k0 >> 2) + kh * 4 + i];
        float* bd = bs + brow * BLD + bq * 8;
#pragma unroll
        for (int i = 0; i < 2; i++)
            ((float4*)bd)[i] = wr4[(k0 >> 2) + bq * 2 + i];
        __syncthreads();
#pragma unroll
        for (int kk = 0; kk < KC; kk += 8) {
            wmma::fragment<wmma::matrix_a, 16, 16, 8, wmma::precision::tf32,
                           wmma::row_major> a;
            wmma::load_matrix_sync(a, as + warp * 16 * ALD + kk, ALD);
#pragma unroll
            for (int q = 0; q < a.num_elements; q++)
                a.x[q] = wmma::__float_to_tf32(a.x[q]);
#pragma unroll
            for (int c = 0; c < 4; c++) {
                wmma::fragment<wmma::matrix_b, 16, 16, 8, wmma::precision::tf32,
                               wmma::col_major> bf;
                wmma::load_matrix_sync(bf, bs + (c * 16) * BLD + kk, BLD);
#pragma unroll
                for (int q = 0; q < bf.num_elements; q++)
                    bf.x[q] = wmma::__float_to_tf32(bf.x[q]);
                wmma::mma_sync(acc[c], a, bf, acc[c]);
            }
        }
        __syncthreads();
    }

#pragma unroll
    for (int c = 0; c < 4; c++)
        wmma::store_matrix_sync(pool + warp * 16 * HLD + c * 16, acc[c], HLD,
                                wmma::mem_row_major);
    __syncthreads();

    int row = tid >> 1;
    int jh  = tid & 1;
    int j0  = jh * 32;
    int n   = nb + row;
    float s1p = 0.0f, s2p = 0.0f;
    float hv[32];
#pragma unroll
    for (int i = 0; i < 32; i++) {
        float v = pool[row * HLD + j0 + i] + b1[j0 + i];
        v = fmaxf(v, 0.0f);
        hv[i] = v;
        s1p += v * gw[j0 + i];
        s2p += v * gw[NH + j0 + i];
    }
    if (n < NN) {
#pragma unroll
        for (int i = 0; i < 32; i += 4)
            *(float4*)(g_h + n * NH + j0 + i) =
                make_float4(hv[i], hv[i + 1], hv[i + 2], hv[i + 3]);
#pragma unroll
        for (int i = 0; i < 32; i += 8) {
            float4 pk;
            pk.x = pack_h2(hv[i    ], hv[i + 1]);
            pk.y = pack_h2(hv[i + 2], hv[i + 3]);
            pk.z = pack_h2(hv[i + 4], hv[i + 5]);
            pk.w = pack_h2(hv[i + 6], hv[i + 7]);
            *(float4*)&g_hh[n * 32 + (j0 + i) / 2] = pk;
        }
    }
    s1p += __shfl_xor_sync(0xffffffff, s1p, 1);
    s2p += __shfl_xor_sync(0xffffffff, s2p, 1);
    if (jh == 0 && n < NN) { g_snA[2 * n] = s1p; g_s2[n] = s2p; }
}

// ---- 8-lane-group agg machinery ----
// Per edge: 1 LDS.64 {byteoff, nrm}, 1 IADD, 1 LDG.128 (8 lanes = 128B row),
// 4 cvt, 8 FFMA, 1 FADD — minimal issue slots.

// stage chunk of up to 8 edges: lane8 stages edge base+lane8
#define AGG_STAGE(SN)                                                            \
    {                                                                            \
        int p = base + lane8;                                                    \
        int off = 0; float nm = 0.0f;                                            \
        if (p < e) {                                                             \
            int r = g_srcA[p];                                                   \
            float2 sn = *(const float2*)(SN + 2 * r);                            \
            nm = ftanh(sn.x + s2n) * sn.y;                                       \
            off = r << 7;  /* byte offset of fp16 row (64*2B=128B) */            \
        }                                                                        \
        s_ed[gp][lane8] = make_int2(off, __float_as_int(nm));                    \
    }

#define AGG_EDGE(QQ, NM)                                                         \
    {                                                                            \
        float2 c0 = __half22float2(*(__half2*)&QQ.x);                            \
        float2 c1 = __half22float2(*(__half2*)&QQ.y);                            \
        float2 c2 = __half22float2(*(__half2*)&QQ.z);                            \
        float2 c3 = __half22float2(*(__half2*)&QQ.w);                            \
        acc0.x += NM * c0.x; acc0.y += NM * c0.y;                                \
        acc0.z += NM * c1.x; acc0.w += NM * c1.y;                                \
        acc1.x += NM * c2.x; acc1.y += NM * c2.y;                                \
        acc1.z += NM * c3.x; acc1.w += NM * c3.y;                                \
        ns += NM;                                                                \
    }

#define AGG_GATHER(HH)                                                           \
    {                                                                            \
        int cnt = e - base; if (cnt > 8) cnt = 8;                                \
        const char* hb = (const char*)(HH);                                      \
        int ii = 0;                                                              \
        for (; ii + 4 <= cnt; ii += 4) {                                         \
            int2 e0 = s_ed[gp][ii    ];                                          \
            int2 e1 = s_ed[gp][ii + 1];                                          \
            int2 e2 = s_ed[gp][ii + 2];                                          \
            int2 e3 = s_ed[gp][ii + 3];                                          \
            float4 q0 = *(const float4*)(hb + e0.x + lane_off);                  \
            float4 q1 = *(const float4*)(hb + e1.x + lane_off);                  \
            float4 q2 = *(const float4*)(hb + e2.x + lane_off);                  \
            float4 q3 = *(const float4*)(hb + e3.x + lane_off);                  \
            float m0 = __int_as_float(e0.y);                                     \
            float m1 = __int_as_float(e1.y);                                     \
            float m2 = __int_as_float(e2.y);                                     \
            float m3 = __int_as_float(e3.y);                                     \
            AGG_EDGE(q0, m0) AGG_EDGE(q1, m1) AGG_EDGE(q2, m2) AGG_EDGE(q3, m3)  \
        }                                                                        \
        for (; ii < cnt; ii++) {                                                 \
            int2 ee = s_ed[gp][ii];                                              \
            float4 qq = *(const float4*)(hb + ee.x + lane_off);                  \
            float mm = __int_as_float(ee.y);                                     \
            AGG_EDGE(qq, mm)                                                     \
        }                                                                        \
    }

// layer-0 aggregation (8-lane group per node) + layer-1 gate scalars
__global__ __launch_bounds__(AGG_THREADS) void k_agg0(const float* __restrict__ gw_next,
                                                      const float* __restrict__ gb) {
    __shared__ int2 s_ed[AGG_NPB][8];
    int tid   = threadIdx.x;
    int gp    = tid >> 3;                   // group in block (0..63)
    int lane8 = tid & 7;
    int gsh   = ((tid >> 3) & 3) * 8;       // group shift within warp
    unsigned mask = 0xFFu << gsh;
    int n = blockIdx.x * AGG_NPB + gp;
    if (n >= NN) return;

    int b = n << 7;
    int e = b + g_fill[n];
    float s2n = g_s2[n] + gb[0];
    float4 acc0 = make_float4(0.f, 0.f, 0.f, 0.f);
    float4 acc1 = make_float4(0.f, 0.f, 0.f, 0.f);
    float  ns = 0.0f;
    int lane_off = lane8 * 16;              // byte offset within 128B row
    int j8 = lane8 * 8;

    for (int base = b; base < e; base += 8) {
        AGG_STAGE(g_snA)
        __syncwarp(mask);
        AGG_GATHER(g_hh)
        __syncwarp(mask);
    }

    float4 hs0 = *(const float4*)(g_h + n * NH + j8);
    float4 hs1 = *(const float4*)(g_h + n * NH + j8 + 4);
    float ci = g_ci[n];
    float4 ho0, ho1;
    ho0.x = EPSR * hs0.x + (acc0.x + hs0.x * ns) * ci;
    ho0.y = EPSR * hs0.y + (acc0.y + hs0.y * ns) * ci;
    ho0.z = EPSR * hs0.z + (acc0.z + hs0.z * ns) * ci;
    ho0.w = EPSR * hs0.w + (acc0.w + hs0.w * ns) * ci;
    ho1.x = EPSR * hs1.x + (acc1.x + hs1.x * ns) * ci;
    ho1.y = EPSR * hs1.y + (acc1.y + hs1.y * ns) * ci;
    ho1.z = EPSR * hs1.z + (acc1.z + hs1.z * ns) * ci;
    ho1.w = EPSR * hs1.w + (acc1.w + hs1.w * ns) * ci;
    *(float4*)(g_h2 + n * NH + j8)     = ho0;
    *(float4*)(g_h2 + n * NH + j8 + 4) = ho1;
    {
        float4 pk;
        pk.x = pack_h2(ho0.x, ho0.y);
        pk.y = pack_h2(ho0.z, ho0.w);
        pk.z = pack_h2(ho1.x, ho1.y);
        pk.w = pack_h2(ho1.z, ho1.w);
        *(float4*)&g_hh2[n * 32 + lane8 * 4] = pk;
    }

    float4 ga0 = *(const float4*)(gw_next + j8);
    float4 ga1 = *(const float4*)(gw_next + j8 + 4);
    float4 gb0 = *(const float4*)(gw_next + NH + j8);
    float4 gb1 = *(const float4*)(gw_next + NH + j8 + 4);
    float p1 = ho0.x * ga0.x + ho0.y * ga0.y + ho0.z * ga0.z + ho0.w * ga0.w
             + ho1.x * ga1.x + ho1.y * ga1.y + ho1.z * ga1.z + ho1.w * ga1.w;
    float p2 = ho0.x * gb0.x + ho0.y * gb0.y + ho0.z * gb0.z + ho0.w * gb0.w
             + ho1.x * gb1.x + ho1.y * gb1.y + ho1.z * gb1.z + ho1.w * gb1.w;
#pragma unroll
    for (int off = 4; off > 0; off >>= 1) {
        p1 += __shfl_xor_sync(mask, p1, off);
        p2 += __shfl_xor_sync(mask, p2, off);
    }
    if (lane8 == 0) { g_snB[2 * n] = p1; g_s2[n] = p2; }
}

// layer-1 aggregation fused with classifier + log_softmax
__global__ __launch_bounds__(AGG_THREADS) void k_agg1_out(const float* __restrict__ gb,
                                                          const float* __restrict__ W2,
                                                          const float* __restrict__ b2,
                                                          float* __restrict__ out) {
    __shared__ int2  s_ed[AGG_NPB][8];
    __shared__ float s_h[AGG_NPB][NH];
    __shared__ float sW2t[NH * NC];
    __shared__ float sb2[NC];

    int tid   = threadIdx.x;
    int gp    = tid >> 3;
    int lane8 = tid & 7;
    unsigned mask = 0xFFu << (((tid >> 3) & 3) * 8);
    int n = blockIdx.x * AGG_NPB + gp;

    for (int idx = tid; idx < NC * NH; idx += AGG_THREADS) {
        int c = idx >> 6, j = idx & 63;
        sW2t[j * NC + c] = W2[idx];
    }
    if (tid < NC) sb2[tid] = b2[tid];
    __syncthreads();
    if (n >= NN) return;

    int b = n << 7;
    int e = b + g_fill[n];
    float s2n = g_s2[n] + gb[1];
    float4 acc0 = make_float4(0.f, 0.f, 0.f, 0.f);
    float4 acc1 = make_float4(0.f, 0.f, 0.f, 0.f);
    float  ns = 0.0f;
    int lane_off = lane8 * 16;
    int j8 = lane8 * 8;

    for (int base = b; base < e; base += 8) {
        AGG_STAGE(g_snB)
        __syncwarp(mask);
        AGG_GATHER(g_hh2)
        __syncwarp(mask);
    }

    float4 hs0 = *(const float4*)(g_h2 + n * NH + j8);
    float4 hs1 = *(const float4*)(g_h2 + n * NH + j8 + 4);
    float4 rw0 = *(const float4*)(g_h  + n * NH + j8);
    float4 rw1 = *(const float4*)(g_h  + n * NH + j8 + 4);
    float ci = g_ci[n];
    float4 ho0, ho1;
    ho0.x = EPSR * rw0.x + (acc0.x + hs0.x * ns) * ci;
    ho0.y = EPSR * rw0.y + (acc0.y + hs0.y * ns) * ci;
    ho0.z = EPSR * rw0.z + (acc0.z + hs0.z * ns) * ci;
    ho0.w = EPSR * rw0.w + (acc0.w + hs0.w * ns) * ci;
    ho1.x = EPSR * rw1.x + (acc1.x + hs1.x * ns) * ci;
    ho1.y = EPSR * rw1.y + (acc1.y + hs1.y * ns) * ci;
    ho1.z = EPSR * rw1.z + (acc1.z + hs1.z * ns) * ci;
    ho1.w = EPSR * rw1.w + (acc1.w + hs1.w * ns) * ci;
    *(float4*)&s_h[gp][j8]     = ho0;
    *(float4*)&s_h[gp][j8 + 4] = ho1;
    __syncwarp(mask);

    // classifier: lane8 handles classes lane8 + 8k, k = 0..4
    float lg[5];
#pragma unroll
    for (int k = 0; k < 5; k++) lg[k] = sb2[lane8 + 8 * k];
#pragma unroll 8
    for (int j = 0; j < NH; j++) {
        float hv = s_h[gp][j];
        const float* wrow = &sW2t[j * NC];
#pragma unroll
        for (int k = 0; k < 5; k++) lg[k] += hv * wrow[lane8 + 8 * k];
    }
    float m = lg[0];
#pragma unroll
    for (int k = 1; k < 5; k++) m = fmaxf(m, lg[k]);
#pragma unroll
    for (int off = 4; off > 0; off >>= 1)
        m = fmaxf(m, __shfl_xor_sync(mask, m, off));
    float s = 0.0f;
#pragma unroll
    for (int k = 0; k < 5; k++) s += expf(lg[k] - m);
#pragma unroll
    for (int off = 4; off > 0; off >>= 1)
        s += __shfl_xor_sync(mask, s, off);
    float lse = m + logf(s);
    float* o = out + (size_t)n * NC;
#pragma unroll
    for (int k = 0; k < 5; k++) o[lane8 + 8 * k] = lg[k] - lse;
}

extern "C" void kernel_launch(void* const* d_in, const int* in_sizes, int n_in,
                              void* d_out, int out_size) {
    const float* x  = (const float*)d_in[0];
    const int*   ei = (const int*)d_in[1];    // int32 (jax x64 disabled)
    const float* W1 = (const float*)d_in[2];
    const float* b1 = (const float*)d_in[3];
    const float* W2 = (const float*)d_in[4];
    const float* b2 = (const float*)d_in[5];
    const float* gw = (const float*)d_in[6];
    const float* gb = (const float*)d_in[7];
    float* out = (float*)d_out;

    static cudaStream_t sB = nullptr;
    static cudaEvent_t evRoot = nullptr, evJoinB = nullptr;
    static void* pDeg = nullptr; static void* pFill = nullptr;
    if (!sB) {
        cudaStreamCreateWithFlags(&sB, cudaStreamNonBlocking);
        cudaEventCreateWithFlags(&evRoot, cudaEventDisableTiming);
        cudaEventCreateWithFlags(&evJoinB, cudaEventDisableTiming);
        cudaGetSymbolAddress(&pDeg, g_deg);
        cudaGetSymbolAddress(&pFill, g_fill);
    }

    const int B = 256;

    cudaEventRecord(evRoot, 0);

    // branch B: gemm
    cudaStreamWaitEvent(sB, evRoot, 0);
    k_gemm1<<<(NN + MT - 1) / MT, 256, 0, sB>>>(x, W1, b1, gw);
    cudaEventRecord(evJoinB, sB);

    // default: memsets -> fused bucket(+deg) -> nodeprep
    cudaMemsetAsync(pDeg, 0, NN * sizeof(int), 0);
    cudaMemsetAsync(pFill, 0, NN * sizeof(int), 0);
    k_bucket<<<(NE / 8 + B - 1) / B, B>>>(ei);
    k_nodeprep<<<(NN + B - 1) / B, B>>>();

    cudaStreamWaitEvent(0, evJoinB, 0);

    k_agg0<<<(NN + AGG_NPB - 1) / AGG_NPB, AGG_THREADS>>>(gw + 2 * NH, gb);
    k_agg1_out<<<(NN + AGG_NPB - 1) / AGG_NPB, AGG_THREADS>>>(gb, W2, b2, out);
}

// round 16
// speedup vs baseline: 1.0855x; 1.0157x over previous
#include <cuda_runtime.h>
#include <cuda_fp16.h>
#include <mma.h>
using namespace nvcuda;

#define NN 50000
#define NE 800000
#define NF 256
#define NH 64
#define NC 40
#define EPSR 0.3f
#define CAP 64                        // fixed per-node slot capacity (Poisson(16): P(>64)≈0)
#define MT 128                        // gemm M-tile (nodes per block)
#define KC 32                         // gemm K-chunk
#define ALD 36                        // A smem leading dim
#define BLD 36                        // B smem leading dim
#define HLD 68                        // epilogue smem leading dim
#define AGG_NPB 64                    // nodes per agg block (8-lane group each)
#define AGG_THREADS (8 * AGG_NPB)     // 512

// ---- device scratch ----
__device__ __align__(128) int     g_deg[NN];
__device__ __align__(128) int     g_fill[NN];      // doubles as incoming-count after bucket
__device__ __align__(128) float   g_ci[NN];        // nd[n]/max(cnt,1)
__device__ __align__(128) float   g_s2[NN];
__device__ __align__(128) float   g_snA[2 * NN];   // {s1_layer0, nd}
__device__ __align__(128) float   g_snB[2 * NN];   // {s1_layer1, nd}
__device__ __align__(128) int     g_srcA[NN * CAP];
__device__ __align__(128) float   g_h[NN * NH];    // layer-0 h == raw (fp32)
__device__ __align__(128) float   g_h2[NN * NH];   // layer-1 input (fp32)
__device__ __align__(128) __half2 g_hh[NN * NH / 2];
__device__ __align__(128) __half2 g_hh2[NN * NH / 2];

__device__ __forceinline__ float ftanh(float x) {
    x = fminf(fmaxf(x, -20.0f), 20.0f);
    float t = __expf(2.0f * x);
    return __fdividef(t - 1.0f, t + 1.0f);
}

__device__ __forceinline__ float pack_h2(float a, float b) {
    __half2 h = __floats2half2_rn(a, b);
    return *(float*)&h;
}

// fused bucketing + degree histogram: 8 edges per thread
__global__ void k_bucket(const int* __restrict__ ei) {
    int t = blockIdx.x * blockDim.x + threadIdx.x;
    if (t >= NE / 8) return;
    int4 ra = ((const int4*)ei)[2 * t];
    int4 rb = ((const int4*)ei)[2 * t + 1];
    int4 ca = ((const int4*)(ei + NE))[2 * t];
    int4 cb = ((const int4*)(ei + NE))[2 * t + 1];
    atomicAdd(&g_deg[ra.x], 1);
    atomicAdd(&g_deg[ra.y], 1);
    atomicAdd(&g_deg[ra.z], 1);
    atomicAdd(&g_deg[ra.w], 1);
    atomicAdd(&g_deg[rb.x], 1);
    atomicAdd(&g_deg[rb.y], 1);
    atomicAdd(&g_deg[rb.z], 1);
    atomicAdd(&g_deg[rb.w], 1);
    int s0 = atomicAdd(&g_fill[ca.x], 1);
    int s1 = atomicAdd(&g_fill[ca.y], 1);
    int s2 = atomicAdd(&g_fill[ca.z], 1);
    int s3 = atomicAdd(&g_fill[ca.w], 1);
    int s4 = atomicAdd(&g_fill[cb.x], 1);
    int s5 = atomicAdd(&g_fill[cb.y], 1);
    int s6 = atomicAdd(&g_fill[cb.z], 1);
    int s7 = atomicAdd(&g_fill[cb.w], 1);
    g_srcA[(ca.x << 6) + s0] = ra.x;
    g_srcA[(ca.y << 6) + s1] = ra.y;
    g_srcA[(ca.z << 6) + s2] = ra.z;
    g_srcA[(ca.w << 6) + s3] = ra.w;
    g_srcA[(cb.x << 6) + s4] = rb.x;
    g_srcA[(cb.y << 6) + s5] = rb.y;
    g_srcA[(cb.z << 6) + s6] = rb.z;
    g_srcA[(cb.w << 6) + s7] = rb.w;
}

// per-node prep (cnt comes from fill after bucket)
__global__ void k_nodeprep() {
    int i = blockIdx.x * blockDim.x + threadIdx.x;
    if (i >= NN) return;
    int d = g_deg[i]; if (d < 1) d = 1;
    float nd = rsqrtf((float)d);
    int c = g_fill[i]; if (c < 1) c = 1;
    g_ci[i] = nd / (float)c;
    g_snA[2 * i + 1] = nd;
    g_snB[2 * i + 1] = nd;
}

__device__ __forceinline__ float4 tf32_4(float4 v) {
    v.x = wmma::__float_to_tf32(v.x);
    v.y = wmma::__float_to_tf32(v.y);
    v.z = wmma::__float_to_tf32(v.z);
    v.w = wmma::__float_to_tf32(v.w);
    return v;
}

// tf32 wmma GEMM, 128x64 block tile; operands converted to tf32 at staging.
__global__ __launch_bounds__(256) void k_gemm1(const float* __restrict__ x,
                                               const float* __restrict__ W1,
                                               const float* __restrict__ b1,
                                               const float* __restrict__ gw) {
    __shared__ float pool[MT * HLD];          // 128*68 floats = 34.8 KB
    float* as = pool;                          // [128][ALD]
    float* bs = pool + MT * ALD;               // [64][BLD]

    int tid = threadIdx.x;
    int nb = blockIdx.x * MT;
    int warp = tid >> 5;                       // 0..7 : 16-row band

    wmma::fragment<wmma::accumulator, 16, 16, 8, float> acc[4];
#pragma unroll
    for (int c = 0; c < 4; c++) wmma::fill_fragment(acc[c], 0.0f);

    int arow = tid >> 1;                       // 0..127
    int kh   = tid & 1;                        // 0..1 : 16-float half
    int xrow = nb + arow; if (xrow >= NN) xrow = NN - 1;
    const float4* xr = (const float4*)(x + (size_t)xrow * NF);
    int brow = tid >> 2;                       // 0..63
    int bq   = tid & 3;                        // 0..3 : 8-float quarter
    const float4* wr4 = (const float4*)(W1 + (size_t)brow * NF);

    for (int k0 = 0; k0 < NF; k0 += KC) {
        float* ad = as + arow * ALD + kh * 16;
#pragma unroll
        for (int i = 0; i < 4; i++)
            ((float4*)ad)[i] = tf32_4(xr[(k0 >> 2) + kh * 4 + i]);
        float* bd = bs + brow * BLD + bq * 8;
#pragma unroll
        for (int i = 0; i < 2; i++)
            ((float4*)bd)[i] = tf32_4(wr4[(k0 >> 2) + bq * 2 + i]);
        __syncthreads();
#pragma unroll
        for (int kk = 0; kk < KC; kk += 8) {
            wmma::fragment<wmma::matrix_a, 16, 16, 8, wmma::precision::tf32,
                           wmma::row_major> a;
            wmma::load_matrix_sync(a, as + warp * 16 * ALD + kk, ALD);
#pragma unroll
            for (int c = 0; c < 4; c++) {
                wmma::fragment<wmma::matrix_b, 16, 16, 8, wmma::precision::tf32,
                               wmma::col_major> bf;
                wmma::load_matrix_sync(bf, bs + (c * 16) * BLD + kk, BLD);
                wmma::mma_sync(acc[c], a, bf, acc[c]);
            }
        }
        __syncthreads();
    }

#pragma unroll
    for (int c = 0; c < 4; c++)
        wmma::store_matrix_sync(pool + warp * 16 * HLD + c * 16, acc[c], HLD,
                                wmma::mem_row_major);
    __syncthreads();

    int row = tid >> 1;
    int jh  = tid & 1;
    int j0  = jh * 32;
    int n   = nb + row;
    float s1p = 0.0f, s2p = 0.0f;
    float hv[32];
#pragma unroll
    for (int i = 0; i < 32; i++) {
        float v = pool[row * HLD + j0 + i] + b1[j0 + i];
        v = fmaxf(v, 0.0f);
        hv[i] = v;
        s1p += v * gw[j0 + i];
        s2p += v * gw[NH + j0 + i];
    }
    if (n < NN) {
#pragma unroll
        for (int i = 0; i < 32; i += 4)
            *(float4*)(g_h + n * NH + j0 + i) =
                make_float4(hv[i], hv[i + 1], hv[i + 2], hv[i + 3]);
#pragma unroll
        for (int i = 0; i < 32; i += 8) {
            float4 pk;
            pk.x = pack_h2(hv[i    ], hv[i + 1]);
            pk.y = pack_h2(hv[i + 2], hv[i + 3]);
            pk.z = pack_h2(hv[i + 4], hv[i + 5]);
            pk.w = pack_h2(hv[i + 6], hv[i + 7]);
            *(float4*)&g_hh[n * 32 + (j0 + i) / 2] = pk;
        }
    }
    s1p += __shfl_xor_sync(0xffffffff, s1p, 1);
    s2p += __shfl_xor_sync(0xffffffff, s2p, 1);
    if (jh == 0 && n < NN) { g_snA[2 * n] = s1p; g_s2[n] = s2p; }
}

// ---- 8-lane-group agg: shfl-broadcast, zero-padded 8-edge chunks, no syncs ----

#define AGG_EDGE(QQ, NM)                                                         \
    {                                                                            \
        float2 c0 = __half22float2(*(__half2*)&QQ.x);                            \
        float2 c1 = __half22float2(*(__half2*)&QQ.y);                            \
        float2 c2 = __half22float2(*(__half2*)&QQ.z);                            \
        float2 c3 = __half22float2(*(__half2*)&QQ.w);                            \
        acc0.x += NM * c0.x; acc0.y += NM * c0.y;                                \
        acc0.z += NM * c1.x; acc0.w += NM * c1.y;                                \
        acc1.x += NM * c2.x; acc1.y += NM * c2.y;                                \
        acc1.z += NM * c3.x; acc1.w += NM * c3.y;                                \
        ns += NM;                                                                \
    }

// chunk of 8 edges: lane stages its edge (zero-padded), shfl-broadcast within group
#define AGG_CHUNK(SN, HH)                                                        \
    {                                                                            \
        int p = base + lane8;                                                    \
        int off = 0; float nm = 0.0f;                                            \
        if (p < e) {                                                             \
            int r = g_srcA[p];                                                   \
            float2 sn = *(const float2*)(SN + 2 * r);                            \
            nm = ftanh(sn.x + s2n) * sn.y;                                       \
            off = r << 7;  /* byte offset of fp16 row */                         \
        }                                                                        \
        const char* hb = (const char*)(HH);                                      \
        _Pragma("unroll")                                                        \
        for (int k = 0; k < 8; k++) {                                            \
            int   offk = __shfl_sync(mask, off, k, 8);                           \
            float nmk  = __shfl_sync(mask, nm,  k, 8);                           \
            float4 q = *(const float4*)(hb + offk + lane_off);                   \
            AGG_EDGE(q, nmk)                                                     \
        }                                                                        \
    }

// layer-0 aggregation (8-lane group per node) + layer-1 gate scalars
__global__ __launch_bounds__(AGG_THREADS) void k_agg0(const float* __restrict__ gw_next,
                                                      const float* __restrict__ gb) {
    int tid   = threadIdx.x;
    int gp    = tid >> 3;                   // group in block (0..63)
    int lane8 = tid & 7;
    unsigned mask = 0xFFu << (((tid >> 3) & 3) * 8);
    int n = blockIdx.x * AGG_NPB + gp;
    if (n >= NN) return;

    int b = n << 6;
    int e = b + g_fill[n];
    float s2n = g_s2[n] + gb[0];
    float4 acc0 = make_float4(0.f, 0.f, 0.f, 0.f);
    float4 acc1 = make_float4(0.f, 0.f, 0.f, 0.f);
    float  ns = 0.0f;
    int lane_off = lane8 * 16;              // byte offset within 128B row
    int j8 = lane8 * 8;

    for (int base = b; base < e; base += 8) {
        AGG_CHUNK(g_snA, g_hh)
    }

    float4 hs0 = *(const float4*)(g_h + n * NH + j8);
    float4 hs1 = *(const float4*)(g_h + n * NH + j8 + 4);
    float ci = g_ci[n];
    float4 ho0, ho1;
    ho0.x = EPSR * hs0.x + (acc0.x + hs0.x * ns) * ci;
    ho0.y = EPSR * hs0.y + (acc0.y + hs0.y * ns) * ci;
    ho0.z = EPSR * hs0.z + (acc0.z + hs0.z * ns) * ci;
    ho0.w = EPSR * hs0.w + (acc0.w + hs0.w * ns) * ci;
    ho1.x = EPSR * hs1.x + (acc1.x + hs1.x * ns) * ci;
    ho1.y = EPSR * hs1.y + (acc1.y + hs1.y * ns) * ci;
    ho1.z = EPSR * hs1.z + (acc1.z + hs1.z * ns) * ci;
    ho1.w = EPSR * hs1.w + (acc1.w + hs1.w * ns) * ci;
    *(float4*)(g_h2 + n * NH + j8)     = ho0;
    *(float4*)(g_h2 + n * NH + j8 + 4) = ho1;
    {
        float4 pk;
        pk.x = pack_h2(ho0.x, ho0.y);
        pk.y = pack_h2(ho0.z, ho0.w);
        pk.z = pack_h2(ho1.x, ho1.y);
        pk.w = pack_h2(ho1.z, ho1.w);
        *(float4*)&g_hh2[n * 32 + lane8 * 4] = pk;
    }

    float4 ga0 = *(const float4*)(gw_next + j8);
    float4 ga1 = *(const float4*)(gw_next + j8 + 4);
    float4 gb0 = *(const float4*)(gw_next + NH + j8);
    float4 gb1 = *(const float4*)(gw_next + NH + j8 + 4);
    float p1 = ho0.x * ga0.x + ho0.y * ga0.y + ho0.z * ga0.z + ho0.w * ga0.w
             + ho1.x * ga1.x + ho1.y * ga1.y + ho1.z * ga1.z + ho1.w * ga1.w;
    float p2 = ho0.x * gb0.x + ho0.y * gb0.y + ho0.z * gb0.z + ho0.w * gb0.w
             + ho1.x * gb1.x + ho1.y * gb1.y + ho1.z * gb1.z + ho1.w * gb1.w;
#pragma unroll
    for (int off = 4; off > 0; off >>= 1) {
        p1 += __shfl_xor_sync(mask, p1, off);
        p2 += __shfl_xor_sync(mask, p2, off);
    }
    if (lane8 == 0) { g_snB[2 * n] = p1; g_s2[n] = p2; }
}

// layer-1 aggregation fused with classifier + log_softmax
__global__ __launch_bounds__(AGG_THREADS) void k_agg1_out(const float* __restrict__ gb,
                                                          const float* __restrict__ W2,
                                                          const float* __restrict__ b2,
                                                          float* __restrict__ out) {
    __shared__ float s_h[AGG_NPB][NH];
    __shared__ float sW2t[NH * NC];
    __shared__ float sb2[NC];

    int tid   = threadIdx.x;
    int gp    = tid >> 3;
    int lane8 = tid & 7;
    unsigned mask = 0xFFu << (((tid >> 3) & 3) * 8);
    int n = blockIdx.x * AGG_NPB + gp;

    for (int idx = tid; idx < NC * NH; idx += AGG_THREADS) {
        int c = idx >> 6, j = idx & 63;
        sW2t[j * NC + c] = W2[idx];
    }
    if (tid < NC) sb2[tid] = b2[tid];
    __syncthreads();
    if (n >= NN) return;

    int b = n << 6;
    int e = b + g_fill[n];
    float s2n = g_s2[n] + gb[1];
    float4 acc0 = make_float4(0.f, 0.f, 0.f, 0.f);
    float4 acc1 = make_float4(0.f, 0.f, 0.f, 0.f);
    float  ns = 0.0f;
    int lane_off = lane8 * 16;
    int j8 = lane8 * 8;

    for (int base = b; base < e; base += 8) {
        AGG_CHUNK(g_snB, g_hh2)
    }

    float4 hs0 = *(const float4*)(g_h2 + n * NH + j8);
    float4 hs1 = *(const float4*)(g_h2 + n * NH + j8 + 4);
    float4 rw0 = *(const float4*)(g_h  + n * NH + j8);
    float4 rw1 = *(const float4*)(g_h  + n * NH + j8 + 4);
    float ci = g_ci[n];
    float4 ho0, ho1;
    ho0.x = EPSR * rw0.x + (acc0.x + hs0.x * ns) * ci;
    ho0.y = EPSR * rw0.y + (acc0.y + hs0.y * ns) * ci;
    ho0.z = EPSR * rw0.z + (acc0.z + hs0.z * ns) * ci;
    ho0.w = EPSR * rw0.w + (acc0.w + hs0.w * ns) * ci;
    ho1.x = EPSR * rw1.x + (acc1.x + hs1.x * ns) * ci;
    ho1.y = EPSR * rw1.y + (acc1.y + hs1.y * ns) * ci;
    ho1.z = EPSR * rw1.z + (acc1.z + hs1.z * ns) * ci;
    ho1.w = EPSR * rw1.w + (acc1.w + hs1.w * ns) * ci;
    *(float4*)&s_h[gp][j8]     = ho0;
    *(float4*)&s_h[gp][j8 + 4] = ho1;
    __syncwarp(mask);

    // classifier: lane8 handles classes lane8 + 8k, k = 0..4
    float lg[5];
#pragma unroll
    for (int k = 0; k < 5; k++) lg[k] = sb2[lane8 + 8 * k];
#pragma unroll 8
    for (int j = 0; j < NH; j++) {
        float hv = s_h[gp][j];
        const float* wrow = &sW2t[j * NC];
#pragma unroll
        for (int k = 0; k < 5; k++) lg[k] += hv * wrow[lane8 + 8 * k];
    }
    float m = lg[0];
#pragma unroll
    for (int k = 1; k < 5; k++) m = fmaxf(m, lg[k]);
#pragma unroll
    for (int off = 4; off > 0; off >>= 1)
        m = fmaxf(m, __shfl_xor_sync(mask, m, off));
    float s = 0.0f;
#pragma unroll
    for (int k = 0; k < 5; k++) s += expf(lg[k] - m);
#pragma unroll
    for (int off = 4; off > 0; off >>= 1)
        s += __shfl_xor_sync(mask, s, off);
    float lse = m + logf(s);
    float* o = out + (size_t)n * NC;
#pragma unroll
    for (int k = 0; k < 5; k++) o[lane8 + 8 * k] = lg[k] - lse;
}

extern "C" void kernel_launch(void* const* d_in, const int* in_sizes, int n_in,
                              void* d_out, int out_size) {
    const float* x  = (const float*)d_in[0];
    const int*   ei = (const int*)d_in[1];    // int32 (jax x64 disabled)
    const float* W1 = (const float*)d_in[2];
    const float* b1 = (const float*)d_in[3];
    const float* W2 = (const float*)d_in[4];
    const float* b2 = (const float*)d_in[5];
    const float* gw = (const float*)d_in[6];
    const float* gb = (const float*)d_in[7];
    float* out = (float*)d_out;

    static cudaStream_t sB = nullptr;
    static cudaEvent_t evRoot = nullptr, evJoinB = nullptr;
    static void* pDeg = nullptr; static void* pFill = nullptr;
    if (!sB) {
        cudaStreamCreateWithFlags(&sB, cudaStreamNonBlocking);
        cudaEventCreateWithFlags(&evRoot, cudaEventDisableTiming);
        cudaEventCreateWithFlags(&evJoinB, cudaEventDisableTiming);
        cudaGetSymbolAddress(&pDeg, g_deg);
        cudaGetSymbolAddress(&pFill, g_fill);
    }

    const int B = 256;

    cudaEventRecord(evRoot, 0);

    // branch B: gemm
    cudaStreamWaitEvent(sB, evRoot, 0);
    k_gemm1<<<(NN + MT - 1) / MT, 256, 0, sB>>>(x, W1, b1, gw);
    cudaEventRecord(evJoinB, sB);

    // default: memsets -> fused bucket(+deg) -> nodeprep
    cudaMemsetAsync(pDeg, 0, NN * sizeof(int), 0);
    cudaMemsetAsync(pFill, 0, NN * sizeof(int), 0);
    k_bucket<<<(NE / 8 + B - 1) / B, B>>>(ei);
    k_nodeprep<<<(NN + B - 1) / B, B>>>();

    cudaStreamWaitEvent(0, evJoinB, 0);

    k_agg0<<<(NN + AGG_NPB - 1) / AGG_NPB, AGG_THREADS>>>(gw + 2 * NH, gb);
    k_agg1_out<<<(NN + AGG_NPB - 1) / AGG_NPB, AGG_THREADS>>>(gb, W2, b2, out);
}

// round 17
// speedup vs baseline: 1.1238x; 1.0353x over previous
#include <cuda_runtime.h>
#include <cuda_fp16.h>
#include <mma.h>
using namespace nvcuda;

#define NN 50000
#define NE 800000
#define NF 256
#define NH 64
#define NC 40
#define EPSR 0.3f
#define CAP 64                        // fixed per-node slot capacity (Poisson(16): P(>64)~0)
#define MT 128                        // gemm M-tile (nodes per block)
#define KC 32                         // gemm K-chunk
#define ALD 36                        // A smem leading dim
#define BLD 36                        // B smem leading dim
#define HLD 68                        // epilogue smem leading dim
#define AGG_NPB 64                    // nodes per agg block (8-lane group each)
#define AGG_THREADS (8 * AGG_NPB)     // 512

// ---- device scratch ----
__device__ __align__(128) int     g_zint[2 * NN];  // [0,NN)=deg, [NN,2NN)=fill (one memset)
__device__ __align__(128) float   g_ci[NN];        // nd[n]/max(cnt,1)
__device__ __align__(128) float   g_s2[NN];
__device__ __align__(128) float   g_snA[2 * NN];   // {s1_layer0, nd}
__device__ __align__(128) float   g_snB[2 * NN];   // {s1_layer1, nd}
__device__ __align__(128) int     g_srcA[NN * CAP];
__device__ __align__(128) float   g_h[NN * NH];    // layer-0 h == raw (fp32)
__device__ __align__(128) float   g_h2[NN * NH];   // layer-1 input (fp32)
__device__ __align__(128) __half2 g_hh[NN * NH / 2];
__device__ __align__(128) __half2 g_hh2[NN * NH / 2];

#define g_deg  (g_zint)
#define g_fill (g_zint + NN)

__device__ __forceinline__ float ftanh(float x) {
    x = fminf(fmaxf(x, -20.0f), 20.0f);
    float t = __expf(2.0f * x);
    return __fdividef(t - 1.0f, t + 1.0f);
}

__device__ __forceinline__ float pack_h2(float a, float b) {
    __half2 h = __floats2half2_rn(a, b);
    return *(float*)&h;
}

// fused bucketing + degree histogram: 8 edges per thread
__global__ void k_bucket(const int* __restrict__ ei) {
    int t = blockIdx.x * blockDim.x + threadIdx.x;
    if (t >= NE / 8) return;
    int4 ra = ((const int4*)ei)[2 * t];
    int4 rb = ((const int4*)ei)[2 * t + 1];
    int4 ca = ((const int4*)(ei + NE))[2 * t];
    int4 cb = ((const int4*)(ei + NE))[2 * t + 1];
    atomicAdd(&g_deg[ra.x], 1);
    atomicAdd(&g_deg[ra.y], 1);
    atomicAdd(&g_deg[ra.z], 1);
    atomicAdd(&g_deg[ra.w], 1);
    atomicAdd(&g_deg[rb.x], 1);
    atomicAdd(&g_deg[rb.y], 1);
    atomicAdd(&g_deg[rb.z], 1);
    atomicAdd(&g_deg[rb.w], 1);
    int s0 = atomicAdd(&g_fill[ca.x], 1);
    int s1 = atomicAdd(&g_fill[ca.y], 1);
    int s2 = atomicAdd(&g_fill[ca.z], 1);
    int s3 = atomicAdd(&g_fill[ca.w], 1);
    int s4 = atomicAdd(&g_fill[cb.x], 1);
    int s5 = atomicAdd(&g_fill[cb.y], 1);
    int s6 = atomicAdd(&g_fill[cb.z], 1);
    int s7 = atomicAdd(&g_fill[cb.w], 1);
    g_srcA[(ca.x << 6) + s0] = ra.x;
    g_srcA[(ca.y << 6) + s1] = ra.y;
    g_srcA[(ca.z << 6) + s2] = ra.z;
    g_srcA[(ca.w << 6) + s3] = ra.w;
    g_srcA[(cb.x << 6) + s4] = rb.x;
    g_srcA[(cb.y << 6) + s5] = rb.y;
    g_srcA[(cb.z << 6) + s6] = rb.z;
    g_srcA[(cb.w << 6) + s7] = rb.w;
}

// per-node prep (cnt comes from fill after bucket)
__global__ void k_nodeprep() {
    int i = blockIdx.x * blockDim.x + threadIdx.x;
    if (i >= NN) return;
    int d = g_deg[i]; if (d < 1) d = 1;
    float nd = rsqrtf((float)d);
    int c = g_fill[i]; if (c < 1) c = 1;
    g_ci[i] = nd / (float)c;
    g_snA[2 * i + 1] = nd;
    g_snB[2 * i + 1] = nd;
}

__device__ __forceinline__ float4 tf32_4(float4 v) {
    v.x = wmma::__float_to_tf32(v.x);
    v.y = wmma::__float_to_tf32(v.y);
    v.z = wmma::__float_to_tf32(v.z);
    v.w = wmma::__float_to_tf32(v.w);
    return v;
}

// tf32 wmma GEMM, 128x64 block tile; operands converted to tf32 at staging.
__global__ __launch_bounds__(256) void k_gemm1(const float* __restrict__ x,
                                               const float* __restrict__ W1,
                                               const float* __restrict__ b1,
                                               const float* __restrict__ gw) {
    __shared__ float pool[MT * HLD];          // 128*68 floats = 34.8 KB
    float* as = pool;                          // [128][ALD]
    float* bs = pool + MT * ALD;               // [64][BLD]

    int tid = threadIdx.x;
    int nb = blockIdx.x * MT;
    int warp = tid >> 5;                       // 0..7 : 16-row band

    wmma::fragment<wmma::accumulator, 16, 16, 8, float> acc[4];
#pragma unroll
    for (int c = 0; c < 4; c++) wmma::fill_fragment(acc[c], 0.0f);

    int arow = tid >> 1;                       // 0..127
    int kh   = tid & 1;                        // 0..1 : 16-float half
    int xrow = nb + arow; if (xrow >= NN) xrow = NN - 1;
    const float4* xr = (const float4*)(x + (size_t)xrow * NF);
    int brow = tid >> 2;                       // 0..63
    int bq   = tid & 3;                        // 0..3 : 8-float quarter
    const float4* wr4 = (const float4*)(W1 + (size_t)brow * NF);

    for (int k0 = 0; k0 < NF; k0 += KC) {
        float* ad = as + arow * ALD + kh * 16;
#pragma unroll
        for (int i = 0; i < 4; i++)
            ((float4*)ad)[i] = tf32_4(xr[(k0 >> 2) + kh * 4 + i]);
        float* bd = bs + brow * BLD + bq * 8;
#pragma unroll
        for (int i = 0; i < 2; i++)
            ((float4*)bd)[i] = tf32_4(wr4[(k0 >> 2) + bq * 2 + i]);
        __syncthreads();
#pragma unroll
        for (int kk = 0; kk < KC; kk += 8) {
            wmma::fragment<wmma::matrix_a, 16, 16, 8, wmma::precision::tf32,
                           wmma::row_major> a;
            wmma::load_matrix_sync(a, as + warp * 16 * ALD + kk, ALD);
#pragma unroll
            for (int c = 0; c < 4; c++) {
                wmma::fragment<wmma::matrix_b, 16, 16, 8, wmma::precision::tf32,
                               wmma::col_major> bf;
                wmma::load_matrix_sync(bf, bs + (c * 16) * BLD + kk, BLD);
                wmma::mma_sync(acc[c], a, bf, acc[c]);
            }
        }
        __syncthreads();
    }

#pragma unroll
    for (int c = 0; c < 4; c++)
        wmma::store_matrix_sync(pool + warp * 16 * HLD + c * 16, acc[c], HLD,
                                wmma::mem_row_major);
    __syncthreads();

    int row = tid >> 1;
    int jh  = tid & 1;
    int j0  = jh * 32;
    int n   = nb + row;
    float s1p = 0.0f, s2p = 0.0f;
    float hv[32];
#pragma unroll
    for (int i = 0; i < 32; i++) {
        float v = pool[row * HLD + j0 + i] + b1[j0 + i];
        v = fmaxf(v, 0.0f);
        hv[i] = v;
        s1p += v * gw[j0 + i];
        s2p += v * gw[NH + j0 + i];
    }
    if (n < NN) {
#pragma unroll
        for (int i = 0; i < 32; i += 4)
            *(float4*)(g_h + n * NH + j0 + i) =
                make_float4(hv[i], hv[i + 1], hv[i + 2], hv[i + 3]);
#pragma unroll
        for (int i = 0; i < 32; i += 8) {
            float4 pk;
            pk.x = pack_h2(hv[i    ], hv[i + 1]);
            pk.y = pack_h2(hv[i + 2], hv[i + 3]);
            pk.z = pack_h2(hv[i + 4], hv[i + 5]);
            pk.w = pack_h2(hv[i + 6], hv[i + 7]);
            *(float4*)&g_hh[n * 32 + (j0 + i) / 2] = pk;
        }
    }
    s1p += __shfl_xor_sync(0xffffffff, s1p, 1);
    s2p += __shfl_xor_sync(0xffffffff, s2p, 1);
    if (jh == 0 && n < NN) { g_snA[2 * n] = s1p; g_s2[n] = s2p; }
}

// ---- 8-lane-group agg: shfl-broadcast, zero-padded 8-edge chunks, no syncs ----

#define AGG_EDGE(QQ, NM)                                                         \
    {                                                                            \
        float2 c0 = __half22float2(*(__half2*)&QQ.x);                            \
        float2 c1 = __half22float2(*(__half2*)&QQ.y);                            \
        float2 c2 = __half22float2(*(__half2*)&QQ.z);                            \
        float2 c3 = __half22float2(*(__half2*)&QQ.w);                            \
        acc0.x += NM * c0.x; acc0.y += NM * c0.y;                                \
        acc0.z += NM * c1.x; acc0.w += NM * c1.y;                                \
        acc1.x += NM * c2.x; acc1.y += NM * c2.y;                                \
        acc1.z += NM * c3.x; acc1.w += NM * c3.y;                                \
        ns += NM;                                                                \
    }

#define AGG_CHUNK(SN, HH)                                                        \
    {                                                                            \
        int p = base + lane8;                                                    \
        int off = 0; float nm = 0.0f;                                            \
        if (p < e) {                                                             \
            int r = g_srcA[p];                                                   \
            float2 sn = *(const float2*)(SN + 2 * r);                            \
            nm = ftanh(sn.x + s2n) * sn.y;                                       \
            off = r << 7;  /* byte offset of fp16 row */                         \
        }                                                                        \
        const char* hb = (const char*)(HH);                                      \
        _Pragma("unroll")                                                        \
        for (int k = 0; k < 8; k++) {                                            \
            int   offk = __shfl_sync(mask, off, k, 8);                           \
            float nmk  = __shfl_sync(mask, nm,  k, 8);                           \
            float4 q = *(const float4*)(hb + offk + lane_off);                   \
            AGG_EDGE(q, nmk)                                                     \
        }                                                                        \
    }

// layer-0 aggregation (8-lane group per node) + layer-1 gate scalars
__global__ __launch_bounds__(AGG_THREADS, 3) void k_agg0(const float* __restrict__ gw_next,
                                                         const float* __restrict__ gb) {
    int tid   = threadIdx.x;
    int gp    = tid >> 3;                   // group in block (0..63)
    int lane8 = tid & 7;
    unsigned mask = 0xFFu << (((tid >> 3) & 3) * 8);
    int n = blockIdx.x * AGG_NPB + gp;
    if (n >= NN) return;

    int b = n << 6;
    int e = b + g_fill[n];
    float s2n = g_s2[n] + gb[0];
    float4 acc0 = make_float4(0.f, 0.f, 0.f, 0.f);
    float4 acc1 = make_float4(0.f, 0.f, 0.f, 0.f);
    float  ns = 0.0f;
    int lane_off = lane8 * 16;              // byte offset within 128B row
    int j8 = lane8 * 8;

    for (int base = b; base < e; base += 8) {
        AGG_CHUNK(g_snA, g_hh)
    }

    float4 hs0 = *(const float4*)(g_h + n * NH + j8);
    float4 hs1 = *(const float4*)(g_h + n * NH + j8 + 4);
    float ci = g_ci[n];
    float4 ho0, ho1;
    ho0.x = EPSR * hs0.x + (acc0.x + hs0.x * ns) * ci;
    ho0.y = EPSR * hs0.y + (acc0.y + hs0.y * ns) * ci;
    ho0.z = EPSR * hs0.z + (acc0.z + hs0.z * ns) * ci;
    ho0.w = EPSR * hs0.w + (acc0.w + hs0.w * ns) * ci;
    ho1.x = EPSR * hs1.x + (acc1.x + hs1.x * ns) * ci;
    ho1.y = EPSR * hs1.y + (acc1.y + hs1.y * ns) * ci;
    ho1.z = EPSR * hs1.z + (acc1.z + hs1.z * ns) * ci;
    ho1.w = EPSR * hs1.w + (acc1.w + hs1.w * ns) * ci;
    *(float4*)(g_h2 + n * NH + j8)     = ho0;
    *(float4*)(g_h2 + n * NH + j8 + 4) = ho1;
    {
        float4 pk;
        pk.x = pack_h2(ho0.x, ho0.y);
        pk.y = pack_h2(ho0.z, ho0.w);
        pk.z = pack_h2(ho1.x, ho1.y);
        pk.w = pack_h2(ho1.z, ho1.w);
        *(float4*)&g_hh2[n * 32 + lane8 * 4] = pk;
    }

    float4 ga0 = *(const float4*)(gw_next + j8);
    float4 ga1 = *(const float4*)(gw_next + j8 + 4);
    float4 gb0 = *(const float4*)(gw_next + NH + j8);
    float4 gb1 = *(const float4*)(gw_next + NH + j8 + 4);
    float p1 = ho0.x * ga0.x + ho0.y * ga0.y + ho0.z * ga0.z + ho0.w * ga0.w
             + ho1.x * ga1.x + ho1.y * ga1.y + ho1.z * ga1.z + ho1.w * ga1.w;
    float p2 = ho0.x * gb0.x + ho0.y * gb0.y + ho0.z * gb0.z + ho0.w * gb0.w
             + ho1.x * gb1.x + ho1.y * gb1.y + ho1.z * gb1.z + ho1.w * gb1.w;
#pragma unroll
    for (int off = 4; off > 0; off >>= 1) {
        p1 += __shfl_xor_sync(mask, p1, off);
        p2 += __shfl_xor_sync(mask, p2, off);
    }
    if (lane8 == 0) { g_snB[2 * n] = p1; g_s2[n] = p2; }
}

// layer-1 aggregation fused with classifier + log_softmax
__global__ __launch_bounds__(AGG_THREADS, 3) void k_agg1_out(const float* __restrict__ gb,
                                                             const float* __restrict__ W2,
                                                             const float* __restrict__ b2,
                                                             float* __restrict__ out) {
    __shared__ float s_h[AGG_NPB][NH];
    __shared__ float sW2t[NH * NC];
    __shared__ float sb2[NC];

    int tid   = threadIdx.x;
    int gp    = tid >> 3;
    int lane8 = tid & 7;
    unsigned mask = 0xFFu << (((tid >> 3) & 3) * 8);
    int n = blockIdx.x * AGG_NPB + gp;

    for (int idx = tid; idx < NC * NH; idx += AGG_THREADS) {
        int c = idx >> 6, j = idx & 63;
        sW2t[j * NC + c] = W2[idx];
    }
    if (tid < NC) sb2[tid] = b2[tid];
    __syncthreads();
    if (n >= NN) return;

    int b = n << 6;
    int e = b + g_fill[n];
    float s2n = g_s2[n] + gb[1];
    float4 acc0 = make_float4(0.f, 0.f, 0.f, 0.f);
    float4 acc1 = make_float4(0.f, 0.f, 0.f, 0.f);
    float  ns = 0.0f;
    int lane_off = lane8 * 16;
    int j8 = lane8 * 8;

    for (int base = b; base < e; base += 8) {
        AGG_CHUNK(g_snB, g_hh2)
    }

    float4 hs0 = *(const float4*)(g_h2 + n * NH + j8);
    float4 hs1 = *(const float4*)(g_h2 + n * NH + j8 + 4);
    float4 rw0 = *(const float4*)(g_h  + n * NH + j8);
    float4 rw1 = *(const float4*)(g_h  + n * NH + j8 + 4);
    float ci = g_ci[n];
    float4 ho0, ho1;
    ho0.x = EPSR * rw0.x + (acc0.x + hs0.x * ns) * ci;
    ho0.y = EPSR * rw0.y + (acc0.y + hs0.y * ns) * ci;
    ho0.z = EPSR * rw0.z + (acc0.z + hs0.z * ns) * ci;
    ho0.w = EPSR * rw0.w + (acc0.w + hs0.w * ns) * ci;
    ho1.x = EPSR * rw1.x + (acc1.x + hs1.x * ns) * ci;
    ho1.y = EPSR * rw1.y + (acc1.y + hs1.y * ns) * ci;
    ho1.z = EPSR * rw1.z + (acc1.z + hs1.z * ns) * ci;
    ho1.w = EPSR * rw1.w + (acc1.w + hs1.w * ns) * ci;
    *(float4*)&s_h[gp][j8]     = ho0;
    *(float4*)&s_h[gp][j8 + 4] = ho1;
    __syncwarp(mask);

    // classifier: lane8 handles classes lane8 + 8k, k = 0..4
    float lg[5];
#pragma unroll
    for (int k = 0; k < 5; k++) lg[k] = sb2[lane8 + 8 * k];
#pragma unroll 8
    for (int j = 0; j < NH; j++) {
        float hv = s_h[gp][j];
        const float* wrow = &sW2t[j * NC];
#pragma unroll
        for (int k = 0; k < 5; k++) lg[k] += hv * wrow[lane8 + 8 * k];
    }
    float m = lg[0];
#pragma unroll
    for (int k = 1; k < 5; k++) m = fmaxf(m, lg[k]);
#pragma unroll
    for (int off = 4; off > 0; off >>= 1)
        m = fmaxf(m, __shfl_xor_sync(mask, m, off));
    float s = 0.0f;
#pragma unroll
    for (int k = 0; k < 5; k++) s += expf(lg[k] - m);
#pragma unroll
    for (int off = 4; off > 0; off >>= 1)
        s += __shfl_xor_sync(mask, s, off);
    float lse = m + logf(s);
    float* o = out + (size_t)n * NC;
#pragma unroll
    for (int k = 0; k < 5; k++) o[lane8 + 8 * k] = lg[k] - lse;
}

extern "C" void kernel_launch(void* const* d_in, const int* in_sizes, int n_in,
                              void* d_out, int out_size) {
    const float* x  = (const float*)d_in[0];
    const int*   ei = (const int*)d_in[1];    // int32 (jax x64 disabled)
    const float* W1 = (const float*)d_in[2];
    const float* b1 = (const float*)d_in[3];
    const float* W2 = (const float*)d_in[4];
    const float* b2 = (const float*)d_in[5];
    const float* gw = (const float*)d_in[6];
    const float* gb = (const float*)d_in[7];
    float* out = (float*)d_out;

    static cudaStream_t sB = nullptr;
    static cudaEvent_t evRoot = nullptr, evJoinB = nullptr;
    static void* pZ = nullptr;
    if (!sB) {
        cudaStreamCreateWithFlags(&sB, cudaStreamNonBlocking);
        cudaEventCreateWithFlags(&evRoot, cudaEventDisableTiming);
        cudaEventCreateWithFlags(&evJoinB, cudaEventDisableTiming);
        cudaGetSymbolAddress(&pZ, g_zint);
    }

    const int B = 256;

    cudaEventRecord(evRoot, 0);

    // branch B: gemm
    cudaStreamWaitEvent(sB, evRoot, 0);
    k_gemm1<<<(NN + MT - 1) / MT, 256, 0, sB>>>(x, W1, b1, gw);
    cudaEventRecord(evJoinB, sB);

    // default: single memset -> fused bucket(+deg) -> nodeprep
    cudaMemsetAsync(pZ, 0, 2 * NN * sizeof(int), 0);
    k_bucket<<<(NE / 8 + B - 1) / B, B>>>(ei);
    k_nodeprep<<<(NN + B - 1) / B, B>>>();

    cudaStreamWaitEvent(0, evJoinB, 0);

    k_agg0<<<(NN + AGG_NPB - 1) / AGG_NPB, AGG_THREADS>>>(gw + 2 * NH, gb);
    k_agg1_out<<<(NN + AGG_NPB - 1) / AGG_NPB, AGG_THREADS>>>(gb, W2, b2, out);
}